// round 15
// baseline (speedup 1.0000x reference)
#include <cuda_runtime.h>
#include <math.h>

#define BB 4
#define NN 32
#define LL 256
#define HH 64
#define NI 31
#define PP 496
#define NEGV (-1e9f)
#define BPB 32            // blocks per batch; block r owns sites [8r, 8r+8)
#define SB 8
#define NTHR 512
#define NBAR 32

// ---------------- persistent device scratch ----------------
__device__ float g_pool[BB*NN*LL*HH];
__device__ float g_u[BB*NN*LL*HH];
__device__ float g_v[BB*NN*LL*HH];
__device__ float g_part[2*BB*PP*32];       // per-(parity,b,pair,block) score partials
__device__ float g_pmpart[2*BB*32*HH];     // per-(parity,b,block,h) parent-mean partials
__device__ float g_mpart[BB*NN*BPB*HH];    // initial per-node mean partials
__device__ float g_loss[BB];
__device__ unsigned g_cnt[BB*32];
__device__ unsigned g_gen[BB*32];
__device__ unsigned g_done;

// ---------------- smem layout (floats) ----------------
#define OFF_WM1T 0        // 64 x 132
#define OFF_WM2T 8448     // 64 x 68
#define OFF_WS1T 12800    // 64 x 132
#define OFF_WB1T 21248    // 64 x 132
#define OFF_BS1  29696
#define OFF_WS2  29760
#define OFF_BM1  29824
#define OFF_BM2  29888
#define OFF_WD   29952    // 64x4
#define OFF_BD   30208
#define OFF_BB1  30272
#define OFF_WB2  30336
#define OFF_SCORE 30400   // 496 pad 512
#define OFF_RED  30912    // 512
#define OFF_SX   31424    // 8 x 132
#define OFF_SH1  32480    // 8 x 68
#define OFF_SH2  33024    // 8 x 68
#define OFF_UST  33568    // 8 x 68
#define OFF_VST  34112    // 8 x 68
#define OFF_MEANS 34656   // 32 x 64 (block r==1)
#define OFF_WE   36704    // 4 x 64
#define OFF_BE   36960    // 64
#define OFF_BSTG 37024    // 256
#define OFF_BSE  37280    // 192
#define OFF_BRED 37472    // 32
#define SMEM_FLOATS 37504
#define SMEM_BYTES (SMEM_FLOATS*4)

#define BAR1 asm volatile("bar.sync 1, 256;" ::: "memory")
#define BAR2 asm volatile("bar.sync 2, 256;" ::: "memory")
#define ARR3 asm volatile("bar.arrive 3, 512;" ::: "memory")
#define SYN3 asm volatile("bar.sync 3, 512;" ::: "memory")

// f32x2 packed-FP32 helpers (FFMA2): exact per-lane rn arithmetic
__device__ __forceinline__ void ffma2(unsigned long long& acc, unsigned long long a,
                                      unsigned long long b) {
    asm("fma.rn.f32x2 %0, %1, %2, %0;" : "+l"(acc) : "l"(a), "l"(b));
}
__device__ __forceinline__ float f2sum(unsigned long long a, unsigned long long b) {
    float ax, ay, bx, by;
    asm("mov.b64 {%0,%1}, %2;" : "=f"(ax), "=f"(ay) : "l"(a));
    asm("mov.b64 {%0,%1}, %2;" : "=f"(bx), "=f"(by) : "l"(b));
    return (ax + ay) + (bx + by);
}

// per-batch software barrier over BPB co-resident blocks (R5-proven mechanism)
__device__ __forceinline__ void bbar(int b, int id) {
    __syncthreads();
    if (threadIdx.x == 0) {
        unsigned next = (id + 1 == NBAR) ? 0u : (unsigned)(id + 1);
        __threadfence();
        unsigned old = atomicAdd(&g_cnt[b*32], 1u);
        if (old == BPB - 1) {
            g_cnt[b*32] = 0;
            __threadfence();
            atomicExch(&g_gen[b*32], next);
        } else {
            volatile unsigned* gg = &g_gen[b*32];
            while (*gg == (unsigned)id) __nanosleep(20);
        }
        __threadfence();
    }
    __syncthreads();
}

// deferred branch lengths for out_step; runs on warps 8-15 of block r==1 (tt = t-256)
__device__ __forceinline__ void do_branch(float* sm, int b, int out_step, int par,
                                          int psi, int psj, float bb2v,
                                          float* __restrict__ br, int tt) {
    float* stage = sm + OFF_BSTG;
    float* se2   = sm + OFF_BSE;
    float* bred  = sm + OFF_BRED;
    float* smean = sm + OFF_MEANS;
    float* sWb1T = sm + OFF_WB1T;
    float* sbb1  = sm + OFF_BB1;
    float* sWb2  = sm + OFF_WB2;
    {
        int h = tt & 63, g = tt >> 6;
        const float* pp = g_pmpart + ((size_t)(par*BB + b)*32 + g*8)*HH + h;
        float a0 = __ldcg(pp) + __ldcg(pp + HH);
        float a1 = __ldcg(pp + 2*HH) + __ldcg(pp + 3*HH);
        float a2 = __ldcg(pp + 4*HH) + __ldcg(pp + 5*HH);
        float a3 = __ldcg(pp + 6*HH) + __ldcg(pp + 7*HH);
        stage[tt] = (a0 + a1) + (a2 + a3);
    }
    BAR2;
    if (tt < HH) {
        se2[tt]       = (stage[tt] + stage[64+tt] + stage[128+tt] + stage[192+tt]) * (1.f/LL);
        se2[64 + tt]  = smean[psi*HH + tt];
        se2[128 + tt] = smean[psj*HH + tt];
    }
    BAR2;
    float contrib = 0.f;
    if (tt < 128) {
        int which = tt >> 6, h = tt & 63;
        const float* mm = se2 + 64 + which*64;
        const float4* wrow = (const float4*)(sWb1T + h*132);
        float a0 = 0, a1 = 0, a2 = 0, a3 = 0;
#pragma unroll
        for (int k4 = 0; k4 < 16; k4++) {
            float4 w0 = wrow[k4];
            float4 w1 = wrow[16 + k4];
            float4 x0 = *(const float4*)(se2 + k4*4);
            float4 x1 = *(const float4*)(mm + k4*4);
            a0 += x0.x*w0.x; a1 += x0.y*w0.y; a2 += x0.z*w0.z; a3 += x0.w*w0.w;
            a0 += x1.x*w1.x; a1 += x1.y*w1.y; a2 += x1.z*w1.z; a3 += x1.w*w1.w;
        }
        float a = sbb1[h] + ((a0 + a1) + (a2 + a3));
        contrib = fmaxf(a, 0.f) * sWb2[h];
    }
#pragma unroll
    for (int o = 16; o; o >>= 1) contrib += __shfl_xor_sync(0xffffffffu, contrib, o);
    if (tt < 128 && (tt & 31) == 0) bred[tt >> 5] = contrib;
    BAR2;
    if (tt < 2) {
        float x = bred[tt*2] + bred[tt*2 + 1] + bb2v;
        br[b*(NI*2) + 2*out_step + tt] = fmaxf(x, 0.f) + log1pf(expf(-fabsf(x)));
    }
    if (tt < HH) smean[psi*HH + tt] = se2[tt];
}

__global__ __launch_bounds__(NTHR, 1)
void phylo_persistent(const float* __restrict__ leaf, const int* __restrict__ order,
                      const float* __restrict__ We, const float* __restrict__ be,
                      const float* __restrict__ Wm1, const float* __restrict__ bm1,
                      const float* __restrict__ Wm2, const float* __restrict__ bm2,
                      const float* __restrict__ Ws1, const float* __restrict__ bs1,
                      const float* __restrict__ Ws2, const float* __restrict__ bs2,
                      const float* __restrict__ Wd, const float* __restrict__ bd,
                      const float* __restrict__ Wb1, const float* __restrict__ bb1,
                      const float* __restrict__ Wb2, const float* __restrict__ bb2,
                      float* __restrict__ ml, float* __restrict__ anc,
                      float* __restrict__ br, float* __restrict__ lo) {
    extern __shared__ float sm[];
    float* sWm1T = sm + OFF_WM1T;
    float* sWm2T = sm + OFF_WM2T;
    float* sWs1T = sm + OFF_WS1T;
    float* sWb1T = sm + OFF_WB1T;
    float* sbs1  = sm + OFF_BS1;
    float* sWs2  = sm + OFF_WS2;
    float* sbm1  = sm + OFF_BM1;
    float* sbm2  = sm + OFF_BM2;
    float* sWd   = sm + OFF_WD;
    float* sbd   = sm + OFF_BD;
    float* sscore = sm + OFF_SCORE;
    float* red   = sm + OFF_RED;
    float* sx    = sm + OFF_SX;
    float* sh1   = sm + OFF_SH1;
    float* sh2   = sm + OFF_SH2;
    float* sust  = sm + OFF_UST;
    float* svst  = sm + OFF_VST;
    float* sWe   = sm + OFF_WE;
    float* sbe   = sm + OFF_BE;
    float* bred  = sm + OFF_BRED;

    __shared__ unsigned char sPI[PP], sPJ[PP];
    __shared__ unsigned sclades[NI];
    __shared__ unsigned slset[NN];
    __shared__ int sact[NN];
    __shared__ int s_si, s_sj;
    __shared__ float s_loss, s_vmax;

    const int b = blockIdx.x / BPB;
    const int r = blockIdx.x % BPB;
    const int t = threadIdx.x;
    const int lbase = r * SB;
    int barid = 0;

    // ---- load transposed weights + small vectors ----
    for (int idx = t; idx < 128*64; idx += NTHR) {
        int k = idx >> 6, h = idx & 63;
        sWm1T[h*132 + k] = Wm1[idx];
        sWs1T[h*132 + k] = Ws1[idx];
        sWb1T[h*132 + k] = Wb1[idx];
    }
    for (int idx = t; idx < 64*64; idx += NTHR) {
        int k = idx >> 6, h = idx & 63;
        sWm2T[h*68 + k] = Wm2[idx];
    }
    if (t < 64) {
        sbs1[t] = bs1[t]; sWs2[t] = Ws2[t];
        sbm1[t] = bm1[t]; sbm2[t] = bm2[t];
        (sm + OFF_BB1)[t] = bb1[t]; (sm + OFF_WB2)[t] = Wb2[t];
        sbe[t]  = be[t];
    }
    for (int idx = t; idx < 256; idx += NTHR) { sWd[idx] = Wd[idx]; sWe[idx] = We[idx]; }
    if (t < 4) sbd[t] = bd[t];
    for (int p = t; p < PP; p += NTHR) {
        int q = p, ii = 0;
        while (q >= NN - 1 - ii) { q -= NN - 1 - ii; ii++; }
        sPI[p] = (unsigned char)ii; sPJ[p] = (unsigned char)(ii + 1 + q);
    }
    if (t < NN) { slset[t] = 1u << t; sact[t] = 1; }
    if (t == 0) {
        s_loss = 0.f;
        unsigned desc[2*NN - 1];
        for (int n = 0; n < NN; n++) desc[n] = 1u << n;
        for (int s = 0; s < NI; s++) {
            unsigned m = desc[order[(b*NI + s)*2]] | desc[order[(b*NI + s)*2 + 1]];
            desc[NN + s] = m;
            sclades[s] = m;
        }
    }
    float bs2v = __ldg(&bs2[0]);
    float bb2v = __ldg(&bb2[0]);
    __syncthreads();

    const int site = t >> 6, h = t & 63;    // (site, h) load/store mapping
    const int gh = t >> 3, gs = t & 7;      // (h, site) GEMM mapping (Phase A)
    const int l = lbase + site;

    // Phase D per-WARP mappings: warp w owns site w
    const int dw = t >> 5;                  // warp id = site 0..7 (t<256 covers all 8? no: 16 warps)
    const int dl = t & 31;

    // ---- Phase A: embeds + u/v + mean partials for own 8 sites, all 32 nodes ----
    for (int n = 0; n < NN; n++) {
        size_t nb = ((size_t)(b*NN + n)*LL)*HH;
        const float4 lf = __ldg((const float4*)(leaf + ((size_t)(b*NN + n)*LL + l)*4));
        float a = fmaxf(sbe[h] + lf.x*sWe[h] + lf.y*sWe[64+h]
                               + lf.z*sWe[128+h] + lf.w*sWe[192+h], 0.f);
        sx[site*132 + h] = a;
        red[t] = a;
        __syncthreads();
        if (t < 64)
            g_mpart[((size_t)(b*NN + n)*BPB + r)*HH + t] =
                ((red[t] + red[64+t]) + (red[128+t] + red[192+t])) +
                ((red[256+t] + red[320+t]) + (red[384+t] + red[448+t]));
        {
            const ulonglong2* w = (const ulonglong2*)(sWs1T + gh*132);
            const ulonglong2* x = (const ulonglong2*)(sx + gs*132);
            unsigned long long uA=0,uB=0,vA=0,vB=0;
#pragma unroll
            for (int k4 = 0; k4 < 16; k4++) {
                ulonglong2 wu = w[k4];
                ulonglong2 wv = w[16 + k4];
                ulonglong2 xv = x[k4];
                ffma2(uA, wu.x, xv.x); ffma2(uB, wu.y, xv.y);
                ffma2(vA, wv.x, xv.x); ffma2(vB, wv.y, xv.y);
            }
            sust[gs*68 + gh] = f2sum(uA, uB);
            svst[gs*68 + gh] = f2sum(vA, vB);
        }
        __syncthreads();
        size_t ub = nb + (size_t)l*HH + h;
        g_pool[ub] = a;
        g_u[ub] = sust[site*68 + h];
        g_v[ub] = svst[site*68 + h];
        __syncthreads();
    }

    // ---- Phase B: initial score partials (parity 1) ----
    for (int rd = 0; rd < 8; rd++) {
        int uidx = rd*NTHR + t;
        int p = uidx >> 3, st8 = uidx & 7;
        float acc = 0.f;
        if (p < PP) {
            int i = sPI[p], j = sPJ[p];
            const float4* up = (const float4*)(g_u + ((size_t)(b*NN + i)*LL + lbase + st8)*HH);
            const float4* vp = (const float4*)(g_v + ((size_t)(b*NN + j)*LL + lbase + st8)*HH);
            float c0=0,c1=0,c2=0,c3=0;
#pragma unroll
            for (int k4 = 0; k4 < 16; k4++) {
                float4 a = up[k4], c = vp[k4];
                int k = k4*4;
                c0 += fmaxf(a.x + c.x + sbs1[k+0], 0.f)*sWs2[k+0];
                c1 += fmaxf(a.y + c.y + sbs1[k+1], 0.f)*sWs2[k+1];
                c2 += fmaxf(a.z + c.z + sbs1[k+2], 0.f)*sWs2[k+2];
                c3 += fmaxf(a.w + c.w + sbs1[k+3], 0.f)*sWs2[k+3];
            }
            acc = (c0 + c1) + (c2 + c3);
        }
        acc += __shfl_down_sync(0xffffffffu, acc, 4);
        acc += __shfl_down_sync(0xffffffffu, acc, 2);
        acc += __shfl_down_sync(0xffffffffu, acc, 1);
        if (p < PP && st8 == 0) g_part[(((size_t)1*BB + b)*PP + p)*32 + r] = acc;
    }
    bbar(b, barid++);

    int prev_si = 0, prev_sj = 0;

    // ---- main loop: one barrier per step ----
    for (int s = 0; s < NI; s++) {
        if (t < 256) {
            // ===== warps 0-7: finalize + argmax (replicated) =====
            if (s == 0) {
                for (int p = t; p < PP; p += 256) {
                    const float* gp = g_part + (((size_t)1*BB + b)*PP + p)*32;
                    float a0=0,a1=0,a2=0,a3=0;
#pragma unroll
                    for (int q = 0; q < 32; q += 4) {
                        a0 += __ldcg(gp + q);     a1 += __ldcg(gp + q + 1);
                        a2 += __ldcg(gp + q + 2); a3 += __ldcg(gp + q + 3);
                    }
                    sscore[p] = ((a0+a1)+(a2+a3)) * (1.f/LL) + bs2v;
                }
            } else {
                int o = t >> 3, q = t & 7;
                int fin = (o != prev_si) && sact[o];
                float ps = 0.f;
                int pidx = 0;
                if (fin) {
                    int i = o < prev_si ? o : prev_si;
                    int j = o < prev_si ? prev_si : o;
                    pidx = i*(2*NN - i - 1)/2 + (j - i - 1);
                    const float* gp = g_part + (((size_t)(((s-1) & 1))*BB + b)*PP + pidx)*32 + q;
                    ps = (__ldcg(gp) + __ldcg(gp + 8)) + (__ldcg(gp + 16) + __ldcg(gp + 24));
                }
                ps += __shfl_down_sync(0xffffffffu, ps, 4);
                ps += __shfl_down_sync(0xffffffffu, ps, 2);
                ps += __shfl_down_sync(0xffffffffu, ps, 1);
                if (fin && q == 0) sscore[pidx] = ps * (1.f/LL) + bs2v;
            }
            BAR1;
            // argmax via packed keys (2 pairs per thread)
            unsigned long long key;
            {
                int i0 = sPI[t], j0 = sPJ[t];
                float v0 = (sact[i0] && sact[j0]) ? sscore[t] : NEGV;
                unsigned ub0 = __float_as_uint(v0);
                ub0 = (ub0 & 0x80000000u) ? ~ub0 : (ub0 | 0x80000000u);
                key = ((unsigned long long)ub0 << 32) | (unsigned)(PP - t);
                int p1 = t + 256;
                if (p1 < PP) {
                    int i1 = sPI[p1], j1 = sPJ[p1];
                    float v1 = (sact[i1] && sact[j1]) ? sscore[p1] : NEGV;
                    unsigned ub1 = __float_as_uint(v1);
                    ub1 = (ub1 & 0x80000000u) ? ~ub1 : (ub1 | 0x80000000u);
                    unsigned long long k1 = ((unsigned long long)ub1 << 32) | (unsigned)(PP - p1);
                    if (k1 > key) key = k1;
                }
            }
#pragma unroll
            for (int o = 16; o; o >>= 1) {
                unsigned long long ok = __shfl_xor_sync(0xffffffffu, key, o);
                if (ok > key) key = ok;
            }
            unsigned long long* redk = (unsigned long long*)red;
            if ((t & 31) == 0) redk[t >> 5] = key;
            BAR1;
            if (t < 8) {
                unsigned long long k = redk[t];
#pragma unroll
                for (int o = 4; o; o >>= 1) {
                    unsigned long long ok = __shfl_xor_sync(0xffu, k, o);
                    if (ok > k) k = ok;
                }
                if (t == 0) {
                    int sel = PP - (int)(k & 0xffffffffu);
                    unsigned u = (unsigned)(k >> 32);
                    unsigned bits = (u & 0x80000000u) ? (u ^ 0x80000000u) : ~u;
                    s_vmax = __uint_as_float(bits);
                    s_si = sPI[sel]; s_sj = sPJ[sel];
                }
            }
            if (r == 0) ARR3;
        } else {
            int tt = t - 256;
            if (r == 1) {
                // ===== warps 8-15 of block 1: means (s==0) or deferred branch =====
                if (s == 0) {
                    float* smean = sm + OFF_MEANS;
                    for (int idx = tt; idx < NN*HH; idx += 256) {
                        int n = idx >> 6, hh = idx & 63;
                        const float* mp = g_mpart + ((size_t)(b*NN + n)*BPB)*HH + hh;
                        float a0=0,a1=0,a2=0,a3=0;
#pragma unroll
                        for (int q = 0; q < 32; q += 4) {
                            a0 += __ldcg(mp + q*HH);       a1 += __ldcg(mp + (q+1)*HH);
                            a2 += __ldcg(mp + (q+2)*HH);   a3 += __ldcg(mp + (q+3)*HH);
                        }
                        smean[idx] = ((a0+a1)+(a2+a3)) * (1.f/LL);
                    }
                } else {
                    do_branch(sm, b, s - 1, (s - 1) & 1, prev_si, prev_sj, bb2v, br, tt);
                }
            } else if (r == 0) {
                // ===== warps 8-15 of block 0: ml + loss for step s =====
                SYN3;
                float vmax = s_vmax;
                float e, cm, av;
                {
                    int i0 = sPI[tt], j0 = sPJ[tt];
                    int vld0 = sact[i0] && sact[j0];
                    float v0 = vld0 ? sscore[tt] : NEGV;
                    ml[((size_t)b*NI + s)*PP + tt] = v0;
                    unsigned mg0 = slset[i0] | slset[j0];
                    float cm0 = 0.f;
                    if (vld0) { for (int q = 0; q < NI; q++) if (mg0 == sclades[q]) { cm0 = 1.f; break; } }
                    e = expf(v0 - vmax); cm = cm0; av = cm0 * (vmax - v0);
                    int p1 = tt + 256;
                    if (p1 < PP) {
                        int i1 = sPI[p1], j1 = sPJ[p1];
                        int vld1 = sact[i1] && sact[j1];
                        float v1 = vld1 ? sscore[p1] : NEGV;
                        ml[((size_t)b*NI + s)*PP + p1] = v1;
                        unsigned mg1 = slset[i1] | slset[j1];
                        float cm1 = 0.f;
                        if (vld1) { for (int q = 0; q < NI; q++) if (mg1 == sclades[q]) { cm1 = 1.f; break; } }
                        e += expf(v1 - vmax); cm += cm1; av += cm1 * (vmax - v1);
                    }
                }
#pragma unroll
                for (int o = 16; o; o >>= 1) {
                    e  += __shfl_xor_sync(0xffffffffu, e, o);
                    cm += __shfl_xor_sync(0xffffffffu, cm, o);
                    av += __shfl_xor_sync(0xffffffffu, av, o);
                }
                if ((tt & 31) == 0) {
                    int w = tt >> 5;
                    bred[w] = e; bred[8 + w] = cm; bred[16 + w] = av;
                }
                BAR2;
                if (tt == 0) {
                    float S = 0, C = 0, A = 0;
#pragma unroll
                    for (int w = 0; w < 8; w++) { S += bred[w]; C += bred[8+w]; A += bred[16+w]; }
                    float logz = logf(S);
                    if (C > 0.f) s_loss += (A + logz * C) / fmaxf(C, 1.f);
                }
            }
        }
        __syncthreads();   // join; s_si/s_sj visible

        const int si = s_si, sj = s_sj;
        const size_t bi = ((size_t)(b*NN + si)*LL)*HH;
        const size_t bj = ((size_t)(b*NN + sj)*LL)*HH;

        // ===== Phase D: parent MLP — 8 independent per-warp chains (1 site each) =====
        // Warps 0-7 own sites 0-7; warps 8-15 mirror the same sites (idle-safe: they
        // recompute identical values into the same smem slots? NO — only warps 0-7 work;
        // warps 8-15 skip straight to the join sync.)
        if (t == 0) {
            slset[si] |= slset[sj];
            slset[sj] = 0u;
            sact[sj] = 0;
        }
        if (dw < 8) {
            const int dsite = dw;
            const int dgl = lbase + dsite;
            // load x row (128 floats) via float2 per lane
            {
                float2 xi = *(const float2*)(g_pool + bi + (size_t)dgl*HH + 2*dl);
                float2 xj = *(const float2*)(g_pool + bj + (size_t)dgl*HH + 2*dl);
                *(float2*)(sx + dsite*132 + 2*dl) = xi;
                *(float2*)(sx + dsite*132 + 64 + 2*dl) = xj;
            }
            __syncwarp();
            const int h0 = dl, h1 = dl + 32;
            // layer 1: h0, h1
            {
                const ulonglong2* w0 = (const ulonglong2*)(sWm1T + h0*132);
                const ulonglong2* w1 = (const ulonglong2*)(sWm1T + h1*132);
                const ulonglong2* x  = (const ulonglong2*)(sx + dsite*132);
                unsigned long long aA0=0,aB0=0,aA1=0,aB1=0;
#pragma unroll
                for (int k4 = 0; k4 < 32; k4++) {
                    ulonglong2 xv = x[k4];
                    ulonglong2 wv0 = w0[k4];
                    ulonglong2 wv1 = w1[k4];
                    ffma2(aA0, wv0.x, xv.x); ffma2(aB0, wv0.y, xv.y);
                    ffma2(aA1, wv1.x, xv.x); ffma2(aB1, wv1.y, xv.y);
                }
                sh1[dsite*68 + h0] = fmaxf(sbm1[h0] + f2sum(aA0, aB0), 0.f);
                sh1[dsite*68 + h1] = fmaxf(sbm1[h1] + f2sum(aA1, aB1), 0.f);
            }
            __syncwarp();
            // layer 2
            {
                const ulonglong2* w0 = (const ulonglong2*)(sWm2T + h0*68);
                const ulonglong2* w1 = (const ulonglong2*)(sWm2T + h1*68);
                const ulonglong2* x  = (const ulonglong2*)(sh1 + dsite*68);
                unsigned long long aA0=0,aB0=0,aA1=0,aB1=0;
#pragma unroll
                for (int k4 = 0; k4 < 16; k4++) {
                    ulonglong2 xv = x[k4];
                    ulonglong2 wv0 = w0[k4];
                    ulonglong2 wv1 = w1[k4];
                    ffma2(aA0, wv0.x, xv.x); ffma2(aB0, wv0.y, xv.y);
                    ffma2(aA1, wv1.x, xv.x); ffma2(aB1, wv1.y, xv.y);
                }
                float c0 = fmaxf(sbm2[h0] + f2sum(aA0, aB0), 0.f);
                float c1 = fmaxf(sbm2[h1] + f2sum(aA1, aB1), 0.f);
                sh2[dsite*68 + h0] = c0;
                sh2[dsite*68 + h1] = c1;
                g_pool[bi + (size_t)dgl*HH + h0] = c0;
                g_pool[bi + (size_t)dgl*HH + h1] = c1;
            }
            __syncwarp();
            // u/v projection
            {
                const ulonglong2* w0 = (const ulonglong2*)(sWs1T + h0*132);
                const ulonglong2* w1 = (const ulonglong2*)(sWs1T + h1*132);
                const ulonglong2* x  = (const ulonglong2*)(sh2 + dsite*68);
                unsigned long long u0A=0,u0B=0,v0A=0,v0B=0,u1A=0,u1B=0,v1A=0,v1B=0;
#pragma unroll
                for (int k4 = 0; k4 < 16; k4++) {
                    ulonglong2 xv = x[k4];
                    ulonglong2 wu0 = w0[k4];
                    ulonglong2 wv0 = w0[16 + k4];
                    ulonglong2 wu1 = w1[k4];
                    ulonglong2 wv1 = w1[16 + k4];
                    ffma2(u0A, wu0.x, xv.x); ffma2(u0B, wu0.y, xv.y);
                    ffma2(v0A, wv0.x, xv.x); ffma2(v0B, wv0.y, xv.y);
                    ffma2(u1A, wu1.x, xv.x); ffma2(u1B, wu1.y, xv.y);
                    ffma2(v1A, wv1.x, xv.x); ffma2(v1B, wv1.y, xv.y);
                }
                float su0 = f2sum(u0A, u0B), sv0 = f2sum(v0A, v0B);
                float su1 = f2sum(u1A, u1B), sv1 = f2sum(v1A, v1B);
                sust[dsite*68 + h0] = su0;  sust[dsite*68 + h1] = su1;
                svst[dsite*68 + h0] = sv0;  svst[dsite*68 + h1] = sv1;
                g_u[bi + (size_t)dgl*HH + h0] = su0;
                g_u[bi + (size_t)dgl*HH + h1] = su1;
                g_v[bi + (size_t)dgl*HH + h0] = sv0;
                g_v[bi + (size_t)dgl*HH + h1] = sv1;
            }
        }
        __syncthreads();   // all sites' sust/svst/sh2 ready for E / anc / pmpart

        // ===== Phase E: rescore partials for pairs touching si =====
        {
            int o = t >> 4, es = (t >> 1) & 7, half = t & 1;
            int doit = sact[o] && (o != si);
            float acc = 0.f;
            int pidx = 0;
            if (doit) {
                int i = o < si ? o : si;
                int j = o < si ? si : o;
                pidx = i*(2*NN - i - 1)/2 + (j - i - 1);
                const float4* stp = (const float4*)(((o < si) ? svst : sust) + es*68);
                const float4* gop = (const float4*)(((o < si) ? g_u : g_v) +
                                    ((size_t)(b*NN + o)*LL + lbase + es)*HH);
                float c0=0,c1=0,c2=0,c3=0;
#pragma unroll
                for (int q = 0; q < 8; q++) {
                    int k4 = half*8 + q;
                    float4 gv = gop[k4];
                    float4 sv4 = stp[k4];
                    int k = k4*4;
                    c0 += fmaxf(gv.x + sv4.x + sbs1[k+0], 0.f)*sWs2[k+0];
                    c1 += fmaxf(gv.y + sv4.y + sbs1[k+1], 0.f)*sWs2[k+1];
                    c2 += fmaxf(gv.z + sv4.z + sbs1[k+2], 0.f)*sWs2[k+2];
                    c3 += fmaxf(gv.w + sv4.w + sbs1[k+3], 0.f)*sWs2[k+3];
                }
                acc = (c0+c1)+(c2+c3);
            }
            acc += __shfl_down_sync(0xffffffffu, acc, 1);
            acc += __shfl_down_sync(0xffffffffu, acc, 2);
            acc += __shfl_down_sync(0xffffffffu, acc, 4);
            acc += __shfl_down_sync(0xffffffffu, acc, 8);
            if (doit && (t & 15) == 0)
                g_part[((size_t)(s & 1)*BB + b)*PP*32 + (size_t)pidx*32 + r] = acc;
        }

        // ===== anc output (reads sh2, off critical path) =====
        if (t < 32) {
            int as = t >> 2, ch = t & 3;
            const float* h2 = sh2 + as*68;
            float a0=0,a1=0,a2=0,a3=0;
#pragma unroll
            for (int k = 0; k < 64; k += 4) {
                a0 += h2[k]   * sWd[k*4 + ch];
                a1 += h2[k+1] * sWd[(k+1)*4 + ch];
                a2 += h2[k+2] * sWd[(k+2)*4 + ch];
                a3 += h2[k+3] * sWd[(k+3)*4 + ch];
            }
            anc[(((size_t)b*NI + s)*LL + lbase + as)*4 + ch] = sbd[ch] + ((a0+a1)+(a2+a3));
        }
        // ===== pmpart (sum sh2 over sites) =====
        else if (t >= 64 && t < 128) {
            int hh = t - 64;
            float a0 = sh2[hh] + sh2[68 + hh];
            float a1 = sh2[136 + hh] + sh2[204 + hh];
            float a2 = sh2[272 + hh] + sh2[340 + hh];
            float a3 = sh2[408 + hh] + sh2[476 + hh];
            g_pmpart[((size_t)((s & 1)*BB + b)*32 + r)*HH + hh] = ((a0+a1)+(a2+a3));
        }

        prev_si = si; prev_sj = sj;
        bbar(b, barid++);
    }

    // ---- epilogue ----
    if (r == 1 && t >= 256)
        do_branch(sm, b, NI - 1, (NI - 1) & 1, prev_si, prev_sj, bb2v, br, t - 256);
    if (r == 0 && t == 0) {
        g_loss[b] = s_loss;
        __threadfence();
        unsigned old = atomicAdd(&g_done, 1u);
        if (old == BB - 1) {
            g_done = 0;
            __threadfence();
            lo[0] = 0.25f * (__ldcg(&g_loss[0]) + __ldcg(&g_loss[1]) +
                             __ldcg(&g_loss[2]) + __ldcg(&g_loss[3]));
        }
    }
}

// ---------------- host ----------------
extern "C" void kernel_launch(void* const* d_in, const int* in_sizes, int n_in,
                              void* d_out, int out_size) {
    const float* leaf = (const float*)d_in[0];
    const int*   order = (const int*)d_in[1];
    const float* We  = (const float*)d_in[2];
    const float* be  = (const float*)d_in[3];
    const float* Wm1 = (const float*)d_in[4];
    const float* bm1 = (const float*)d_in[5];
    const float* Wm2 = (const float*)d_in[6];
    const float* bm2 = (const float*)d_in[7];
    const float* Ws1 = (const float*)d_in[8];
    const float* bs1 = (const float*)d_in[9];
    const float* Ws2 = (const float*)d_in[10];
    const float* bs2 = (const float*)d_in[11];
    const float* Wd  = (const float*)d_in[12];
    const float* bd  = (const float*)d_in[13];
    const float* Wb1 = (const float*)d_in[14];
    const float* bb1 = (const float*)d_in[15];
    const float* Wb2 = (const float*)d_in[16];
    const float* bb2 = (const float*)d_in[17];

    float* out = (float*)d_out;
    float* ml  = out;                              // [B, NI, P]
    float* anc = ml + (size_t)BB * NI * PP;        // [B, NI, L, 4]
    float* br  = anc + (size_t)BB * NI * LL * 4;   // [B, NI*2]
    float* lo  = br + (size_t)BB * NI * 2;         // scalar

    cudaFuncSetAttribute(phylo_persistent,
                         cudaFuncAttributeMaxDynamicSharedMemorySize, SMEM_BYTES);
    phylo_persistent<<<BB*BPB, NTHR, SMEM_BYTES>>>(
        leaf, order, We, be, Wm1, bm1, Wm2, bm2, Ws1, bs1, Ws2, bs2,
        Wd, bd, Wb1, bb1, Wb2, bb2, ml, anc, br, lo);
}

// round 16
// speedup vs baseline: 1.0606x; 1.0606x over previous
#include <cuda_runtime.h>
#include <math.h>

#define BB 4
#define NN 32
#define LL 256
#define HH 64
#define NI 31
#define PP 496
#define NEGV (-1e9f)
#define BPB 32            // blocks per batch; block r owns sites [8r, 8r+8)
#define SB 8
#define NTHR 512
#define NBAR 32

// ---------------- persistent device scratch ----------------
__device__ float g_pool[BB*NN*LL*HH];
__device__ float g_u[BB*NN*LL*HH];
__device__ float g_v[BB*NN*LL*HH];
__device__ float g_part[2*BB*PP*32];       // per-(parity,b,pair,block) score partials
__device__ float g_pmpart[2*BB*32*HH];     // per-(parity,b,block,h) parent-mean partials
__device__ float g_mpart[BB*NN*BPB*HH];    // initial per-node mean partials
__device__ float g_loss[BB];
__device__ unsigned g_cnt[BB*32];
__device__ unsigned g_gen[BB*32];
__device__ unsigned g_done;

// ---------------- smem layout (floats) ----------------
#define OFF_WM1T 0        // 64 x 132
#define OFF_WM2T 8448     // 64 x 68
#define OFF_WS1T 12800    // 64 x 132
#define OFF_WB1T 21248    // 64 x 132
#define OFF_BS1  29696
#define OFF_WS2  29760
#define OFF_BM1  29824
#define OFF_BM2  29888
#define OFF_WD   29952    // 64x4
#define OFF_BD   30208
#define OFF_BB1  30272
#define OFF_WB2  30336
#define OFF_SCORE 30400   // 496 pad 512
#define OFF_RED  30912    // 512
#define OFF_SX   31424    // 8 x 132
#define OFF_SH1  32480    // 8 x 68
#define OFF_SH2  33024    // 8 x 68
#define OFF_UST  33568    // 8 x 68
#define OFF_VST  34112    // 8 x 68
#define OFF_MEANS 34656   // 32 x 64 (block r==1)
#define OFF_WE   36704    // 4 x 64
#define OFF_BE   36960    // 64
#define OFF_BSTG 37024    // 256
#define OFF_BSE  37280    // 192
#define OFF_BRED 37472    // 32
#define SMEM_FLOATS 37504
#define SMEM_BYTES (SMEM_FLOATS*4)

#define BAR1 asm volatile("bar.sync 1, 256;" ::: "memory")
#define BAR2 asm volatile("bar.sync 2, 256;" ::: "memory")
#define ARR3 asm volatile("bar.arrive 3, 512;" ::: "memory")
#define SYN3 asm volatile("bar.sync 3, 512;" ::: "memory")
#define BARWG(id) asm volatile("bar.sync %0, 128;" :: "r"(id) : "memory")

// f32x2 packed-FP32 helpers (FFMA2): exact per-lane rn arithmetic
__device__ __forceinline__ void ffma2(unsigned long long& acc, unsigned long long a,
                                      unsigned long long b) {
    asm("fma.rn.f32x2 %0, %1, %2, %0;" : "+l"(acc) : "l"(a), "l"(b));
}
__device__ __forceinline__ float f2sum(unsigned long long a, unsigned long long b) {
    float ax, ay, bx, by;
    asm("mov.b64 {%0,%1}, %2;" : "=f"(ax), "=f"(ay) : "l"(a));
    asm("mov.b64 {%0,%1}, %2;" : "=f"(bx), "=f"(by) : "l"(b));
    return (ax + ay) + (bx + by);
}

// per-batch software barrier over BPB co-resident blocks (R5-proven mechanism)
__device__ __forceinline__ void bbar(int b, int id) {
    __syncthreads();
    if (threadIdx.x == 0) {
        unsigned next = (id + 1 == NBAR) ? 0u : (unsigned)(id + 1);
        __threadfence();
        unsigned old = atomicAdd(&g_cnt[b*32], 1u);
        if (old == BPB - 1) {
            g_cnt[b*32] = 0;
            __threadfence();
            atomicExch(&g_gen[b*32], next);
        } else {
            volatile unsigned* gg = &g_gen[b*32];
            while (*gg == (unsigned)id) __nanosleep(20);
        }
        __threadfence();
    }
    __syncthreads();
}

// deferred branch lengths for out_step; runs on warps 8-15 of block r==1 (tt = t-256)
__device__ __forceinline__ void do_branch(float* sm, int b, int out_step, int par,
                                          int psi, int psj, float bb2v,
                                          float* __restrict__ br, int tt) {
    float* stage = sm + OFF_BSTG;
    float* se2   = sm + OFF_BSE;
    float* bred  = sm + OFF_BRED;
    float* smean = sm + OFF_MEANS;
    float* sWb1T = sm + OFF_WB1T;
    float* sbb1  = sm + OFF_BB1;
    float* sWb2  = sm + OFF_WB2;
    {
        int h = tt & 63, g = tt >> 6;
        const float* pp = g_pmpart + ((size_t)(par*BB + b)*32 + g*8)*HH + h;
        float a0 = __ldcg(pp) + __ldcg(pp + HH);
        float a1 = __ldcg(pp + 2*HH) + __ldcg(pp + 3*HH);
        float a2 = __ldcg(pp + 4*HH) + __ldcg(pp + 5*HH);
        float a3 = __ldcg(pp + 6*HH) + __ldcg(pp + 7*HH);
        stage[tt] = (a0 + a1) + (a2 + a3);
    }
    BAR2;
    if (tt < HH) {
        se2[tt]       = (stage[tt] + stage[64+tt] + stage[128+tt] + stage[192+tt]) * (1.f/LL);
        se2[64 + tt]  = smean[psi*HH + tt];
        se2[128 + tt] = smean[psj*HH + tt];
    }
    BAR2;
    float contrib = 0.f;
    if (tt < 128) {
        int which = tt >> 6, h = tt & 63;
        const float* mm = se2 + 64 + which*64;
        const float4* wrow = (const float4*)(sWb1T + h*132);
        float a0 = 0, a1 = 0, a2 = 0, a3 = 0;
#pragma unroll
        for (int k4 = 0; k4 < 16; k4++) {
            float4 w0 = wrow[k4];
            float4 w1 = wrow[16 + k4];
            float4 x0 = *(const float4*)(se2 + k4*4);
            float4 x1 = *(const float4*)(mm + k4*4);
            a0 += x0.x*w0.x; a1 += x0.y*w0.y; a2 += x0.z*w0.z; a3 += x0.w*w0.w;
            a0 += x1.x*w1.x; a1 += x1.y*w1.y; a2 += x1.z*w1.z; a3 += x1.w*w1.w;
        }
        float a = sbb1[h] + ((a0 + a1) + (a2 + a3));
        contrib = fmaxf(a, 0.f) * sWb2[h];
    }
#pragma unroll
    for (int o = 16; o; o >>= 1) contrib += __shfl_xor_sync(0xffffffffu, contrib, o);
    if (tt < 128 && (tt & 31) == 0) bred[tt >> 5] = contrib;
    BAR2;
    if (tt < 2) {
        float x = bred[tt*2] + bred[tt*2 + 1] + bb2v;
        br[b*(NI*2) + 2*out_step + tt] = fmaxf(x, 0.f) + log1pf(expf(-fabsf(x)));
    }
    if (tt < HH) smean[psi*HH + tt] = se2[tt];
}

__global__ __launch_bounds__(NTHR, 1)
void phylo_persistent(const float* __restrict__ leaf, const int* __restrict__ order,
                      const float* __restrict__ We, const float* __restrict__ be,
                      const float* __restrict__ Wm1, const float* __restrict__ bm1,
                      const float* __restrict__ Wm2, const float* __restrict__ bm2,
                      const float* __restrict__ Ws1, const float* __restrict__ bs1,
                      const float* __restrict__ Ws2, const float* __restrict__ bs2,
                      const float* __restrict__ Wd, const float* __restrict__ bd,
                      const float* __restrict__ Wb1, const float* __restrict__ bb1,
                      const float* __restrict__ Wb2, const float* __restrict__ bb2,
                      float* __restrict__ ml, float* __restrict__ anc,
                      float* __restrict__ br, float* __restrict__ lo) {
    extern __shared__ float sm[];
    float* sWm1T = sm + OFF_WM1T;
    float* sWm2T = sm + OFF_WM2T;
    float* sWs1T = sm + OFF_WS1T;
    float* sWb1T = sm + OFF_WB1T;
    float* sbs1  = sm + OFF_BS1;
    float* sWs2  = sm + OFF_WS2;
    float* sbm1  = sm + OFF_BM1;
    float* sbm2  = sm + OFF_BM2;
    float* sWd   = sm + OFF_WD;
    float* sbd   = sm + OFF_BD;
    float* sscore = sm + OFF_SCORE;
    float* red   = sm + OFF_RED;
    float* sx    = sm + OFF_SX;
    float* sh1   = sm + OFF_SH1;
    float* sh2   = sm + OFF_SH2;
    float* sust  = sm + OFF_UST;
    float* svst  = sm + OFF_VST;
    float* sWe   = sm + OFF_WE;
    float* sbe   = sm + OFF_BE;
    float* bred  = sm + OFF_BRED;

    __shared__ unsigned char sPI[PP], sPJ[PP];
    __shared__ unsigned sclades[NI];
    __shared__ unsigned slset[NN];
    __shared__ int sact[NN];
    __shared__ int s_si, s_sj;
    __shared__ float s_loss, s_vmax;

    const int b = blockIdx.x / BPB;
    const int r = blockIdx.x % BPB;
    const int t = threadIdx.x;
    const int lbase = r * SB;
    int barid = 0;

    // ---- load transposed weights + small vectors ----
    for (int idx = t; idx < 128*64; idx += NTHR) {
        int k = idx >> 6, h = idx & 63;
        sWm1T[h*132 + k] = Wm1[idx];
        sWs1T[h*132 + k] = Ws1[idx];
        sWb1T[h*132 + k] = Wb1[idx];
    }
    for (int idx = t; idx < 64*64; idx += NTHR) {
        int k = idx >> 6, h = idx & 63;
        sWm2T[h*68 + k] = Wm2[idx];
    }
    if (t < 64) {
        sbs1[t] = bs1[t]; sWs2[t] = Ws2[t];
        sbm1[t] = bm1[t]; sbm2[t] = bm2[t];
        (sm + OFF_BB1)[t] = bb1[t]; (sm + OFF_WB2)[t] = Wb2[t];
        sbe[t]  = be[t];
    }
    for (int idx = t; idx < 256; idx += NTHR) { sWd[idx] = Wd[idx]; sWe[idx] = We[idx]; }
    if (t < 4) sbd[t] = bd[t];
    for (int p = t; p < PP; p += NTHR) {
        int q = p, ii = 0;
        while (q >= NN - 1 - ii) { q -= NN - 1 - ii; ii++; }
        sPI[p] = (unsigned char)ii; sPJ[p] = (unsigned char)(ii + 1 + q);
    }
    if (t < NN) { slset[t] = 1u << t; sact[t] = 1; }
    if (t == 0) {
        s_loss = 0.f;
        unsigned desc[2*NN - 1];
        for (int n = 0; n < NN; n++) desc[n] = 1u << n;
        for (int s = 0; s < NI; s++) {
            unsigned m = desc[order[(b*NI + s)*2]] | desc[order[(b*NI + s)*2 + 1]];
            desc[NN + s] = m;
            sclades[s] = m;
        }
    }
    float bs2v = __ldg(&bs2[0]);
    float bb2v = __ldg(&bb2[0]);
    __syncthreads();

    const int site = t >> 6, h = t & 63;    // (site, h) load/store mapping
    const int gh = t >> 3, gs = t & 7;      // (h, site) GEMM mapping (Phase A)
    const int l = lbase + site;

    // Phase D warpgroup-local mappings: wg owns sites {2wg, 2wg+1}
    const int wg    = t >> 7;               // 0..3
    const int wlid  = t & 127;
    const int dlsite = 2*wg + (wlid >> 6);
    const int dlh    = wlid & 63;
    const int dgh    = wlid >> 1;
    const int dgsite = 2*wg + (wlid & 1);
    const int barwg  = 4 + wg;

    // ---- Phase A: embeds + u/v + mean partials for own 8 sites, all 32 nodes ----
    for (int n = 0; n < NN; n++) {
        size_t nb = ((size_t)(b*NN + n)*LL)*HH;
        const float4 lf = __ldg((const float4*)(leaf + ((size_t)(b*NN + n)*LL + l)*4));
        float a = fmaxf(sbe[h] + lf.x*sWe[h] + lf.y*sWe[64+h]
                               + lf.z*sWe[128+h] + lf.w*sWe[192+h], 0.f);
        sx[site*132 + h] = a;
        red[t] = a;
        __syncthreads();
        if (t < 64)
            g_mpart[((size_t)(b*NN + n)*BPB + r)*HH + t] =
                ((red[t] + red[64+t]) + (red[128+t] + red[192+t])) +
                ((red[256+t] + red[320+t]) + (red[384+t] + red[448+t]));
        {
            const ulonglong2* w = (const ulonglong2*)(sWs1T + gh*132);
            const ulonglong2* x = (const ulonglong2*)(sx + gs*132);
            unsigned long long uA=0,uB=0,vA=0,vB=0;
#pragma unroll
            for (int k4 = 0; k4 < 16; k4++) {
                ulonglong2 wu = w[k4];
                ulonglong2 wv = w[16 + k4];
                ulonglong2 xv = x[k4];
                ffma2(uA, wu.x, xv.x); ffma2(uB, wu.y, xv.y);
                ffma2(vA, wv.x, xv.x); ffma2(vB, wv.y, xv.y);
            }
            sust[gs*68 + gh] = f2sum(uA, uB);
            svst[gs*68 + gh] = f2sum(vA, vB);
        }
        __syncthreads();
        size_t ub = nb + (size_t)l*HH + h;
        g_pool[ub] = a;
        g_u[ub] = sust[site*68 + h];
        g_v[ub] = svst[site*68 + h];
        __syncthreads();
    }

    // ---- Phase B: initial score partials (parity 1) ----
    for (int rd = 0; rd < 8; rd++) {
        int uidx = rd*NTHR + t;
        int p = uidx >> 3, st8 = uidx & 7;
        float acc = 0.f;
        if (p < PP) {
            int i = sPI[p], j = sPJ[p];
            const float4* up = (const float4*)(g_u + ((size_t)(b*NN + i)*LL + lbase + st8)*HH);
            const float4* vp = (const float4*)(g_v + ((size_t)(b*NN + j)*LL + lbase + st8)*HH);
            float c0=0,c1=0,c2=0,c3=0;
#pragma unroll
            for (int k4 = 0; k4 < 16; k4++) {
                float4 a = up[k4], c = vp[k4];
                int k = k4*4;
                c0 += fmaxf(a.x + c.x + sbs1[k+0], 0.f)*sWs2[k+0];
                c1 += fmaxf(a.y + c.y + sbs1[k+1], 0.f)*sWs2[k+1];
                c2 += fmaxf(a.z + c.z + sbs1[k+2], 0.f)*sWs2[k+2];
                c3 += fmaxf(a.w + c.w + sbs1[k+3], 0.f)*sWs2[k+3];
            }
            acc = (c0 + c1) + (c2 + c3);
        }
        acc += __shfl_down_sync(0xffffffffu, acc, 4);
        acc += __shfl_down_sync(0xffffffffu, acc, 2);
        acc += __shfl_down_sync(0xffffffffu, acc, 1);
        if (p < PP && st8 == 0) g_part[(((size_t)1*BB + b)*PP + p)*32 + r] = acc;
    }
    bbar(b, barid++);

    int prev_si = 0, prev_sj = 0;

    // ---- main loop: one barrier per step ----
    for (int s = 0; s < NI; s++) {
        if (t < 256) {
            // ===== warps 0-7: finalize + argmax (replicated) =====
            if (s == 0) {
                for (int p = t; p < PP; p += 256) {
                    const float* gp = g_part + (((size_t)1*BB + b)*PP + p)*32;
                    float a0=0,a1=0,a2=0,a3=0;
#pragma unroll
                    for (int q = 0; q < 32; q += 4) {
                        a0 += __ldcg(gp + q);     a1 += __ldcg(gp + q + 1);
                        a2 += __ldcg(gp + q + 2); a3 += __ldcg(gp + q + 3);
                    }
                    sscore[p] = ((a0+a1)+(a2+a3)) * (1.f/LL) + bs2v;
                }
            } else {
                int o = t >> 3, q = t & 7;
                int fin = (o != prev_si) && sact[o];
                float ps = 0.f;
                int pidx = 0;
                if (fin) {
                    int i = o < prev_si ? o : prev_si;
                    int j = o < prev_si ? prev_si : o;
                    pidx = i*(2*NN - i - 1)/2 + (j - i - 1);
                    const float* gp = g_part + (((size_t)(((s-1) & 1))*BB + b)*PP + pidx)*32 + q;
                    ps = (__ldcg(gp) + __ldcg(gp + 8)) + (__ldcg(gp + 16) + __ldcg(gp + 24));
                }
                ps += __shfl_down_sync(0xffffffffu, ps, 4);
                ps += __shfl_down_sync(0xffffffffu, ps, 2);
                ps += __shfl_down_sync(0xffffffffu, ps, 1);
                if (fin && q == 0) sscore[pidx] = ps * (1.f/LL) + bs2v;
            }
            BAR1;
            // argmax via packed keys (2 pairs per thread)
            unsigned long long key;
            {
                int i0 = sPI[t], j0 = sPJ[t];
                float v0 = (sact[i0] && sact[j0]) ? sscore[t] : NEGV;
                unsigned ub0 = __float_as_uint(v0);
                ub0 = (ub0 & 0x80000000u) ? ~ub0 : (ub0 | 0x80000000u);
                key = ((unsigned long long)ub0 << 32) | (unsigned)(PP - t);
                int p1 = t + 256;
                if (p1 < PP) {
                    int i1 = sPI[p1], j1 = sPJ[p1];
                    float v1 = (sact[i1] && sact[j1]) ? sscore[p1] : NEGV;
                    unsigned ub1 = __float_as_uint(v1);
                    ub1 = (ub1 & 0x80000000u) ? ~ub1 : (ub1 | 0x80000000u);
                    unsigned long long k1 = ((unsigned long long)ub1 << 32) | (unsigned)(PP - p1);
                    if (k1 > key) key = k1;
                }
            }
#pragma unroll
            for (int o = 16; o; o >>= 1) {
                unsigned long long ok = __shfl_xor_sync(0xffffffffu, key, o);
                if (ok > key) key = ok;
            }
            unsigned long long* redk = (unsigned long long*)red;
            if ((t & 31) == 0) redk[t >> 5] = key;
            BAR1;
            if (t < 8) {
                unsigned long long k = redk[t];
#pragma unroll
                for (int o = 4; o; o >>= 1) {
                    unsigned long long ok = __shfl_xor_sync(0xffu, k, o);
                    if (ok > k) k = ok;
                }
                if (t == 0) {
                    int sel = PP - (int)(k & 0xffffffffu);
                    unsigned u = (unsigned)(k >> 32);
                    unsigned bits = (u & 0x80000000u) ? (u ^ 0x80000000u) : ~u;
                    s_vmax = __uint_as_float(bits);
                    s_si = sPI[sel]; s_sj = sPJ[sel];
                }
            }
            if (r == 0) ARR3;
        } else {
            int tt = t - 256;
            if (r == 1) {
                // ===== warps 8-15 of block 1: means (s==0) or deferred branch =====
                if (s == 0) {
                    float* smean = sm + OFF_MEANS;
                    for (int idx = tt; idx < NN*HH; idx += 256) {
                        int n = idx >> 6, hh = idx & 63;
                        const float* mp = g_mpart + ((size_t)(b*NN + n)*BPB)*HH + hh;
                        float a0=0,a1=0,a2=0,a3=0;
#pragma unroll
                        for (int q = 0; q < 32; q += 4) {
                            a0 += __ldcg(mp + q*HH);       a1 += __ldcg(mp + (q+1)*HH);
                            a2 += __ldcg(mp + (q+2)*HH);   a3 += __ldcg(mp + (q+3)*HH);
                        }
                        smean[idx] = ((a0+a1)+(a2+a3)) * (1.f/LL);
                    }
                } else {
                    do_branch(sm, b, s - 1, (s - 1) & 1, prev_si, prev_sj, bb2v, br, tt);
                }
            } else if (r == 0) {
                // ===== warps 8-15 of block 0: ml + loss for step s =====
                SYN3;
                float vmax = s_vmax;
                float e, cm, av;
                {
                    int i0 = sPI[tt], j0 = sPJ[tt];
                    int vld0 = sact[i0] && sact[j0];
                    float v0 = vld0 ? sscore[tt] : NEGV;
                    ml[((size_t)b*NI + s)*PP + tt] = v0;
                    unsigned mg0 = slset[i0] | slset[j0];
                    float cm0 = 0.f;
                    if (vld0) { for (int q = 0; q < NI; q++) if (mg0 == sclades[q]) { cm0 = 1.f; break; } }
                    e = expf(v0 - vmax); cm = cm0; av = cm0 * (vmax - v0);
                    int p1 = tt + 256;
                    if (p1 < PP) {
                        int i1 = sPI[p1], j1 = sPJ[p1];
                        int vld1 = sact[i1] && sact[j1];
                        float v1 = vld1 ? sscore[p1] : NEGV;
                        ml[((size_t)b*NI + s)*PP + p1] = v1;
                        unsigned mg1 = slset[i1] | slset[j1];
                        float cm1 = 0.f;
                        if (vld1) { for (int q = 0; q < NI; q++) if (mg1 == sclades[q]) { cm1 = 1.f; break; } }
                        e += expf(v1 - vmax); cm += cm1; av += cm1 * (vmax - v1);
                    }
                }
#pragma unroll
                for (int o = 16; o; o >>= 1) {
                    e  += __shfl_xor_sync(0xffffffffu, e, o);
                    cm += __shfl_xor_sync(0xffffffffu, cm, o);
                    av += __shfl_xor_sync(0xffffffffu, av, o);
                }
                if ((tt & 31) == 0) {
                    int w = tt >> 5;
                    bred[w] = e; bred[8 + w] = cm; bred[16 + w] = av;
                }
                BAR2;
                if (tt == 0) {
                    float S = 0, C = 0, A = 0;
#pragma unroll
                    for (int w = 0; w < 8; w++) { S += bred[w]; C += bred[8+w]; A += bred[16+w]; }
                    float logz = logf(S);
                    if (C > 0.f) s_loss += (A + logz * C) / fmaxf(C, 1.f);
                }
            }
        }
        __syncthreads();   // join; s_si/s_sj visible

        const int si = s_si, sj = s_sj;
        const size_t bi = ((size_t)(b*NN + si)*LL)*HH;
        const size_t bj = ((size_t)(b*NN + sj)*LL)*HH;

        // ===== Phase D: parent MLP — 4 independent warpgroup chains (2 sites each) =====
        sx[dlsite*132 + dlh]      = g_pool[bi + (size_t)(lbase + dlsite)*HH + dlh];
        sx[dlsite*132 + 64 + dlh] = g_pool[bj + (size_t)(lbase + dlsite)*HH + dlh];
        if (t == 0) {
            slset[si] |= slset[sj];
            slset[sj] = 0u;
            sact[sj] = 0;
        }
        BARWG(barwg);
        {
            const ulonglong2* w = (const ulonglong2*)(sWm1T + dgh*132);
            const ulonglong2* x = (const ulonglong2*)(sx + dgsite*132);
            unsigned long long aA = 0, aB = 0;
#pragma unroll
            for (int k4 = 0; k4 < 32; k4++) {
                ulonglong2 wv = w[k4], xv = x[k4];
                ffma2(aA, wv.x, xv.x); ffma2(aB, wv.y, xv.y);
            }
            sh1[dgsite*68 + dgh] = fmaxf(sbm1[dgh] + f2sum(aA, aB), 0.f);
        }
        BARWG(barwg);
        {
            const ulonglong2* w = (const ulonglong2*)(sWm2T + dgh*68);
            const ulonglong2* x = (const ulonglong2*)(sh1 + dgsite*68);
            unsigned long long aA = 0, aB = 0;
#pragma unroll
            for (int k4 = 0; k4 < 16; k4++) {
                ulonglong2 wv = w[k4], xv = x[k4];
                ffma2(aA, wv.x, xv.x); ffma2(aB, wv.y, xv.y);
            }
            float cval = fmaxf(sbm2[dgh] + f2sum(aA, aB), 0.f);
            sh2[dgsite*68 + dgh] = cval;
            g_pool[bi + (size_t)(lbase + dgsite)*HH + dgh] = cval;
        }
        BARWG(barwg);
        {
            const ulonglong2* w = (const ulonglong2*)(sWs1T + dgh*132);
            const ulonglong2* x = (const ulonglong2*)(sh2 + dgsite*68);
            unsigned long long uA=0,uB=0,vA=0,vB=0;
#pragma unroll
            for (int k4 = 0; k4 < 16; k4++) {
                ulonglong2 wu = w[k4];
                ulonglong2 wv = w[16 + k4];
                ulonglong2 xv = x[k4];
                ffma2(uA, wu.x, xv.x); ffma2(uB, wu.y, xv.y);
                ffma2(vA, wv.x, xv.x); ffma2(vB, wv.y, xv.y);
            }
            float su = f2sum(uA, uB), sv = f2sum(vA, vB);
            sust[dgsite*68 + dgh] = su;
            svst[dgsite*68 + dgh] = sv;
            g_u[bi + (size_t)(lbase + dgsite)*HH + dgh] = su;
            g_v[bi + (size_t)(lbase + dgsite)*HH + dgh] = sv;
        }
        __syncthreads();   // all sites' sust/svst/sh2 ready for E / anc / pmpart

        // ===== Phase E: rescore partials for pairs touching si =====
        {
            int o = t >> 4, es = (t >> 1) & 7, half = t & 1;
            int doit = sact[o] && (o != si);
            float acc = 0.f;
            int pidx = 0;
            if (doit) {
                int i = o < si ? o : si;
                int j = o < si ? si : o;
                pidx = i*(2*NN - i - 1)/2 + (j - i - 1);
                const float4* stp = (const float4*)(((o < si) ? svst : sust) + es*68);
                const float4* gop = (const float4*)(((o < si) ? g_u : g_v) +
                                    ((size_t)(b*NN + o)*LL + lbase + es)*HH);
                float c0=0,c1=0,c2=0,c3=0;
#pragma unroll
                for (int q = 0; q < 8; q++) {
                    int k4 = half*8 + q;
                    float4 gv = gop[k4];
                    float4 sv4 = stp[k4];
                    int k = k4*4;
                    c0 += fmaxf(gv.x + sv4.x + sbs1[k+0], 0.f)*sWs2[k+0];
                    c1 += fmaxf(gv.y + sv4.y + sbs1[k+1], 0.f)*sWs2[k+1];
                    c2 += fmaxf(gv.z + sv4.z + sbs1[k+2], 0.f)*sWs2[k+2];
                    c3 += fmaxf(gv.w + sv4.w + sbs1[k+3], 0.f)*sWs2[k+3];
                }
                acc = (c0+c1)+(c2+c3);
            }
            acc += __shfl_down_sync(0xffffffffu, acc, 1);
            acc += __shfl_down_sync(0xffffffffu, acc, 2);
            acc += __shfl_down_sync(0xffffffffu, acc, 4);
            acc += __shfl_down_sync(0xffffffffu, acc, 8);
            if (doit && (t & 15) == 0)
                g_part[((size_t)(s & 1)*BB + b)*PP*32 + (size_t)pidx*32 + r] = acc;
        }

        // ===== anc output (reads sh2, off critical path) =====
        if (t < 32) {
            int as = t >> 2, ch = t & 3;
            const float* h2 = sh2 + as*68;
            float a0=0,a1=0,a2=0,a3=0;
#pragma unroll
            for (int k = 0; k < 64; k += 4) {
                a0 += h2[k]   * sWd[k*4 + ch];
                a1 += h2[k+1] * sWd[(k+1)*4 + ch];
                a2 += h2[k+2] * sWd[(k+2)*4 + ch];
                a3 += h2[k+3] * sWd[(k+3)*4 + ch];
            }
            anc[(((size_t)b*NI + s)*LL + lbase + as)*4 + ch] = sbd[ch] + ((a0+a1)+(a2+a3));
        }
        // ===== pmpart (sum sh2 over sites) =====
        else if (t >= 64 && t < 128) {
            int hh = t - 64;
            float a0 = sh2[hh] + sh2[68 + hh];
            float a1 = sh2[136 + hh] + sh2[204 + hh];
            float a2 = sh2[272 + hh] + sh2[340 + hh];
            float a3 = sh2[408 + hh] + sh2[476 + hh];
            g_pmpart[((size_t)((s & 1)*BB + b)*32 + r)*HH + hh] = ((a0+a1)+(a2+a3));
        }

        prev_si = si; prev_sj = sj;
        bbar(b, barid++);
    }

    // ---- epilogue ----
    if (r == 1 && t >= 256)
        do_branch(sm, b, NI - 1, (NI - 1) & 1, prev_si, prev_sj, bb2v, br, t - 256);
    if (r == 0 && t == 0) {
        g_loss[b] = s_loss;
        __threadfence();
        unsigned old = atomicAdd(&g_done, 1u);
        if (old == BB - 1) {
            g_done = 0;
            __threadfence();
            lo[0] = 0.25f * (__ldcg(&g_loss[0]) + __ldcg(&g_loss[1]) +
                             __ldcg(&g_loss[2]) + __ldcg(&g_loss[3]));
        }
    }
}

// ---------------- host ----------------
extern "C" void kernel_launch(void* const* d_in, const int* in_sizes, int n_in,
                              void* d_out, int out_size) {
    const float* leaf = (const float*)d_in[0];
    const int*   order = (const int*)d_in[1];
    const float* We  = (const float*)d_in[2];
    const float* be  = (const float*)d_in[3];
    const float* Wm1 = (const float*)d_in[4];
    const float* bm1 = (const float*)d_in[5];
    const float* Wm2 = (const float*)d_in[6];
    const float* bm2 = (const float*)d_in[7];
    const float* Ws1 = (const float*)d_in[8];
    const float* bs1 = (const float*)d_in[9];
    const float* Ws2 = (const float*)d_in[10];
    const float* bs2 = (const float*)d_in[11];
    const float* Wd  = (const float*)d_in[12];
    const float* bd  = (const float*)d_in[13];
    const float* Wb1 = (const float*)d_in[14];
    const float* bb1 = (const float*)d_in[15];
    const float* Wb2 = (const float*)d_in[16];
    const float* bb2 = (const float*)d_in[17];

    float* out = (float*)d_out;
    float* ml  = out;                              // [B, NI, P]
    float* anc = ml + (size_t)BB * NI * PP;        // [B, NI, L, 4]
    float* br  = anc + (size_t)BB * NI * LL * 4;   // [B, NI*2]
    float* lo  = br + (size_t)BB * NI * 2;         // scalar

    cudaFuncSetAttribute(phylo_persistent,
                         cudaFuncAttributeMaxDynamicSharedMemorySize, SMEM_BYTES);
    phylo_persistent<<<BB*BPB, NTHR, SMEM_BYTES>>>(
        leaf, order, We, be, Wm1, bm1, Wm2, bm2, Ws1, bs1, Ws2, bs2,
        Wd, bd, Wb1, bb1, Wb2, bb2, ml, anc, br, lo);
}